// round 10
// baseline (speedup 1.0000x reference)
#include <cuda_runtime.h>
#include <cstdint>

// ---------------------------------------------------------------------------
// QLSTM fused persistent kernel, v6: exclusive-SM scan (occupancy 1).
//   * each gate uses only W[0,:]  -> theta is a scalar per batch element
//   * _expval(theta,U) = alpha + R*cos(theta - phi), E in [-1,1]
//   * f,i,g,o scalars per row -> c[b,:], h[b,:] uniform over hidden dim
// Roles (G = #SM blocks, occ 1 so every block owns an SM):
//   block 0  warps 0-3 : 128 scalar scans fed from smem only, per-warp paced
//            warps 4-7 : z-stagers gmem->smem ring (2 bufs x 16 steps)
//   blocks 1..G-1      : chunk-major projection, 2 rows/iter (8 LDG in flight)
//                        then chunk-by-chunk broadcast gated on g_dw[4]
// ---------------------------------------------------------------------------

#define T_STEPS 256
#define BATCH   128
#define ROWS    (T_STEPS * BATCH)     // 32768
#define DIMQ    256
#define NCH     8
#define CH_T    32                    // scan steps per credit/bcast chunk
#define CHROWS  (CH_T * BATCH)        // 4096 z-rows per chunk
#define REG4    (CHROWS * 128)        // float4 of output per chunk = 524288
#define SEQ_T   16                    // steps per smem buffer
#define NSEQ    (T_STEPS / SEQ_T)     // 16
#define NBUF    2                     // ring depth (2 x 16 x 128 x 16B = 64 KB)

__device__ float4   g_z[ROWS];        // per (t,b): x-projection per gate
__device__ float    g_h[ROWS];        // h scalar per (t,b)
__device__ float    g_cfin[BATCH];    // final c per b
__device__ unsigned g_zcnt[NCH];      // z rows completed per chunk (target 4096)
__device__ unsigned g_dw[4];          // scan chunks completed per scan warp

struct Args {
    const float* x;
    const float* W[4];
    const float* b[4];
    const float* P[4];
    float4* out;
    int G;     // grid size
    int Wp;    // proj warps = (G-1)*8
    int n4;    // out_size / 4
};

// ---------------- sync primitives ----------------
__device__ __forceinline__ void red_release(unsigned* p, unsigned v) {
    asm volatile("red.release.gpu.add.u32 [%0], %1;" :: "l"(p), "r"(v) : "memory");
}
__device__ __forceinline__ unsigned ld_acq(const unsigned* p) {
    unsigned v;
    asm volatile("ld.acquire.gpu.u32 %0, [%1];" : "=r"(v) : "l"(p) : "memory");
    return v;
}
__device__ __forceinline__ void publish(unsigned* p, unsigned v) {
    asm volatile("fence.acq_rel.gpu;" ::: "memory");
    asm volatile("st.relaxed.gpu.u32 [%0], %1;" :: "l"(p), "r"(v) : "memory");
}

// ---------------- math helpers ----------------
__device__ __forceinline__ float2 cmul(float2 a, float2 b) {
    return make_float2(a.x * b.x - a.y * b.y, a.x * b.y + a.y * b.x);
}
__device__ __forceinline__ int chain_perm(int k) {   // CNOT chain = prefix-XOR
    k ^= k >> 1; k ^= k >> 2; k ^= k >> 4;
    return k & 0xFF;
}
__device__ __forceinline__ float rcpf(float x) {
    float r;
    asm("rcp.approx.f32 %0, %1;" : "=f"(r) : "f"(x));
    return r;
}
// sigmoid(x), |x|<=1: odd Taylor deg 9, err <= 2.2e-6
__device__ __forceinline__ float sig_poly(float x) {
    float y = x * x;
    float p = fmaf(y,  2.1356999e-5f, -2.1084600e-4f);
    p = fmaf(y, p,  2.0833333e-3f);
    p = fmaf(y, p, -2.0833333e-2f);
    p = fmaf(y, p,  2.5e-1f);
    return fmaf(x, p, 0.5f);
}
// tanh(x), |x|<~2.8: [7/6] Pade, flattened dependency tree
__device__ __forceinline__ float tanh_pade(float x) {
    float y  = x * x;
    float t1 = fmaf(y, 4725.f, 10395.f);
    float t2 = y + 210.f;
    float y2 = y * y;
    float d  = fmaf(y2, t2, t1);
    float n  = fmaf(y, fmaf(y, 21.f, 1260.f), 10395.f);
    return (x * n) * rcpf(d);
}

// ---------------- init (reset counters each replay) ----------------
__global__ void init_kernel() {
    int i = threadIdx.x;
    if (i < NCH) g_zcnt[i] = 0u;
    if (i < 4)  g_dw[i]   = 0u;
}

// ---------------- fused kernel ----------------
__global__ void __launch_bounds__(256, 1) fused_kernel(Args a) {
    extern __shared__ float4 s_z[];   // [NBUF][SEQ_T][BATCH] = 64 KB (block 0 only)

    const int bid  = blockIdx.x;
    const int tid  = threadIdx.x;
    const int warp = tid >> 5, lane = tid & 31;

    // ============================ block 0: consts + staged scan ============================
    if (bid == 0) {
        __shared__ float2 rot[2][8][2][2];
        __shared__ float2 u0[DIMQ];
        __shared__ float2 u1[DIMQ];
        __shared__ float  rbuf[4][8];
        __shared__ float  s_gate[4][5];        // alpha, R, phi, sW, b0
        __shared__ int    s_prod;              // buffers published by stagers
        __shared__ int    s_cons[4];           // buffers consumed per scan warp

        const int k   = tid;
        const int pk0 = chain_perm(k);
        if (tid == 0) s_prod = 0;
        if (tid < 4)  s_cons[tid] = 0;

        // -------- gate constants (all 256 threads, 4 gates) --------
        for (int g = 0; g < 4; ++g) {
            __syncthreads();
            const float* P = a.P[g];
            if (k < 16) {
                int l = k >> 3, w = k & 7;
                float phi = P[(l * 8 + w) * 3 + 0];
                float th  = P[(l * 8 + w) * 3 + 1];
                float om  = P[(l * 8 + w) * 3 + 2];
                float s, c;
                __sincosf(0.5f * th, &s, &c);
                float hp = 0.5f * (phi + om);
                float hm = 0.5f * (phi - om);
                float2 ep = make_float2(__cosf(hp), -__sinf(hp));
                float2 em = make_float2(__cosf(hm),  __sinf(hm));
                rot[l][w][0][0] = make_float2( ep.x * c,  ep.y * c);
                rot[l][w][0][1] = make_float2(-em.x * s, -em.y * s);
                rot[l][w][1][0] = make_float2( em.x * s, -em.y * s);
                rot[l][w][1][1] = make_float2( ep.x * c, -ep.y * c);
            }
            __syncthreads();

            float2 a0v = make_float2(1.f, 0.f);
            float2 a1v = make_float2(1.f, 0.f);
            #pragma unroll
            for (int w = 0; w < 8; ++w) {
                int kb = (k >> (7 - w)) & 1;
                a0v = cmul(a0v, rot[0][w][kb][0]);
                a1v = cmul(a1v, rot[0][w][kb][(w == 0) ? 1 : 0]);
            }
            u0[pk0] = a0v;
            u1[pk0] = a1v;
            __syncthreads();

            #pragma unroll
            for (int w = 0; w < 8; ++w) {
                int p = 7 - w, m = 1 << p, kb = (k >> p) & 1;
                float2 x0 = u0[k & ~m], x1 = u0[k | m];
                float2 y0 = u1[k & ~m], y1 = u1[k | m];
                __syncthreads();
                float2 r0 = rot[1][w][kb][0];
                float2 r1 = rot[1][w][kb][1];
                u0[k] = make_float2(r0.x * x0.x - r0.y * x0.y + r1.x * x1.x - r1.y * x1.y,
                                    r0.x * x0.y + r0.y * x0.x + r1.x * x1.y + r1.y * x1.x);
                u1[k] = make_float2(r0.x * y0.x - r0.y * y0.y + r1.x * y1.x - r1.y * y1.y,
                                    r0.x * y0.y + r0.y * y0.x + r1.x * y1.y + r1.y * y1.x);
                __syncthreads();
            }

            float2 c0 = u0[k], c1 = u1[k];
            __syncthreads();
            u0[pk0] = c0; u1[pk0] = c1;
            __syncthreads();
            c0 = u0[k]; c1 = u1[k];

            float z0 = (k < 128) ? 1.f : -1.f;
            float A  = z0 * (c0.x * c0.x + c0.y * c0.y);
            float Bv = z0 * (c1.x * c1.x + c1.y * c1.y);
            float Cv = -2.f * z0 * (c0.y * c1.x - c0.x * c1.y);
            const float* W = a.W[g];
            float sw = W[512 + k] + W[768 + k];

            float vals[4] = {A, Bv, Cv, sw};
            #pragma unroll
            for (int i = 0; i < 4; ++i) {
                float xv = vals[i];
                #pragma unroll
                for (int off = 16; off; off >>= 1)
                    xv += __shfl_xor_sync(0xffffffffu, xv, off);
                if (lane == 0) rbuf[i][warp] = xv;
            }
            __syncthreads();
            if (k == 0) {
                float t[4];
                #pragma unroll
                for (int i = 0; i < 4; ++i) {
                    float s = 0.f;
                    #pragma unroll
                    for (int wv = 0; wv < 8; ++wv) s += rbuf[i][wv];
                    t[i] = s;
                }
                float alpha = 0.5f * (t[0] + t[1]);
                float beta  = 0.5f * (t[0] - t[1]);
                float gamma = 0.5f * t[2];
                float R     = sqrtf(beta * beta + gamma * gamma);
                float phi   = (R > 0.f) ? atan2f(gamma, beta) : 0.f;
                s_gate[g][0] = alpha;
                s_gate[g][1] = R;
                s_gate[g][2] = phi;
                s_gate[g][3] = t[3];
                s_gate[g][4] = a.b[g][0];
            }
        }
        __syncthreads();

        volatile int* vprod = &s_prod;
        volatile int* vcons = s_cons;

        if (tid >= BATCH) {
            // ================= warps 4-7: z-stagers (gmem -> smem ring) =================
            const int p = tid - BATCH;   // 0..127
            const float tbf = s_gate[0][4] - s_gate[0][2];
            const float tbi = s_gate[1][4] - s_gate[1][2];
            const float tbg = s_gate[2][4] - s_gate[2][2];
            const float tbo = s_gate[3][4] - s_gate[3][2];

            for (int seq = 0; seq < NSEQ; ++seq) {
                if (p == 0) {
                    if ((seq & 1) == 0) {   // new credit chunk of 32 steps
                        const int c = seq >> 1;
                        while (ld_acq(&g_zcnt[c]) < (unsigned)CHROWS) __nanosleep(64);
                    }
                    // ring space: previous occupant (seq-2) consumed by all warps
                    while (vcons[0] < seq - 1 || vcons[1] < seq - 1 ||
                           vcons[2] < seq - 1 || vcons[3] < seq - 1) {}
                }
                asm volatile("bar.sync 2, 128;" ::: "memory");

                float4* dst = &s_z[(size_t)(seq & (NBUF - 1)) * SEQ_T * BATCH + p];
                const float4* src = &g_z[seq * SEQ_T * BATCH + p];
                #pragma unroll
                for (int half = 0; half < 2; ++half) {
                    float4 zb[8];
                    #pragma unroll
                    for (int s = 0; s < 8; ++s)
                        zb[s] = src[(half * 8 + s) * BATCH];     // 8 LDG in flight
                    #pragma unroll
                    for (int s = 0; s < 8; ++s) {
                        float4 z = zb[s];
                        dst[(half * 8 + s) * BATCH] =
                            make_float4(z.x + tbf, z.y + tbi, z.z + tbg, z.w + tbo);
                    }
                }
                asm volatile("bar.sync 2, 128;" ::: "memory");   // drains STS
                if (p == 0) *vprod = seq + 1;
            }
            return;
        }

        // ================= warps 0-3: scalar scan from smem, per-warp paced ==========
        const int b = tid;
        const float af = s_gate[0][0], Rf = s_gate[0][1], swf = s_gate[0][3];
        const float ai = s_gate[1][0], Ri = s_gate[1][1], swi = s_gate[1][3];
        const float ag = s_gate[2][0], Rg = s_gate[2][1], swg = s_gate[2][3];
        const float ao = s_gate[3][0], Ro = s_gate[3][1], swo = s_gate[3][3];

        float h = 0.f, cc = 0.f;

        #define QSTEP(ZV, T) { \
            float vf = __cosf(fmaf(h, swf, (ZV).x)); \
            float vi = __cosf(fmaf(h, swi, (ZV).y)); \
            float vg = __cosf(fmaf(h, swg, (ZV).z)); \
            float vo = __cosf(fmaf(h, swo, (ZV).w)); \
            float ff = sig_poly(fmaf(Rf, vf, af)); \
            float ii = sig_poly(fmaf(Ri, vi, ai)); \
            float gg = tanh_pade(fmaf(Rg, vg, ag)); \
            float oo = sig_poly(fmaf(Ro, vo, ao)); \
            cc = fmaf(ff, cc, ii * gg); \
            h  = oo * tanh_pade(cc); \
            g_h[(T) * BATCH + b] = h; }

        for (int seq = 0; seq < NSEQ; ++seq) {
            if (lane == 0) { while (*vprod < seq + 1) {} }
            __syncwarp();
            const float4* src = &s_z[(size_t)(seq & (NBUF - 1)) * SEQ_T * BATCH + b];
            const int tbase = seq * SEQ_T;

            float4 zv[4], zw[4];
            #pragma unroll
            for (int s = 0; s < 4; ++s) zv[s] = src[s * BATCH];
            #pragma unroll
            for (int g4 = 0; g4 < SEQ_T; g4 += 4) {
                if (g4 + 4 < SEQ_T) {
                    #pragma unroll
                    for (int s = 0; s < 4; ++s) zw[s] = src[(g4 + 4 + s) * BATCH];
                }
                QSTEP(zv[0], tbase + g4 + 0);
                QSTEP(zv[1], tbase + g4 + 1);
                QSTEP(zv[2], tbase + g4 + 2);
                QSTEP(zv[3], tbase + g4 + 3);
                zv[0] = zw[0]; zv[1] = zw[1]; zv[2] = zw[2]; zv[3] = zw[3];
            }

            if (seq == NSEQ - 1) g_cfin[b] = cc;
            __syncwarp();
            if (lane == 0) {
                vcons[warp] = seq + 1;                        // ring release (smem)
                if (seq & 1) publish(&g_dw[warp], (unsigned)((seq >> 1) + 1));
            }
        }
        #undef QSTEP
        return;
    }

    // ============================ workers ============================
    // -------- PHASE 1: projection, chunk-major, 2 rows per iteration --------
    {
        const int gw = (bid - 1) * 8 + warp;   // 0 .. Wp-1
        const float4* x4 = reinterpret_cast<const float4*>(a.x);

        float4 wv0[4], wv1[4], wv2[4], wv3[4];
        {
            const float4* W0 = reinterpret_cast<const float4*>(a.W[0]);
            const float4* W1 = reinterpret_cast<const float4*>(a.W[1]);
            const float4* W2 = reinterpret_cast<const float4*>(a.W[2]);
            const float4* W3 = reinterpret_cast<const float4*>(a.W[3]);
            #pragma unroll
            for (int it = 0; it < 4; ++it) {
                int e4 = it * 32 + lane;
                wv0[it] = W0[e4]; wv1[it] = W1[e4];
                wv2[it] = W2[e4]; wv3[it] = W3[e4];
            }
        }

        for (int c = 0; c < NCH; ++c) {
            const int cbase = c * CHROWS;
            const int cend  = cbase + CHROWS;
            int done = 0;
            for (int r = cbase + gw; r < cend; r += 2 * a.Wp) {
                const int  r2  = r + a.Wp;
                const bool two = (r2 < cend);
                const float4* xr  = x4 + (size_t)r * 128;
                const float4* xr2 = x4 + (size_t)(two ? r2 : r) * 128;

                float s0 = 0.f, s1 = 0.f, s2 = 0.f, s3 = 0.f;
                float u0v = 0.f, u1v = 0.f, u2v = 0.f, u3v = 0.f;
                #pragma unroll
                for (int it = 0; it < 4; ++it) {
                    float4 xa = xr [it * 32 + lane];   // 8 LDG.128 in flight
                    float4 xb = xr2[it * 32 + lane];
                    s0 = fmaf(xa.x, wv0[it].x, s0); s0 = fmaf(xa.y, wv0[it].y, s0);
                    s0 = fmaf(xa.z, wv0[it].z, s0); s0 = fmaf(xa.w, wv0[it].w, s0);
                    s1 = fmaf(xa.x, wv1[it].x, s1); s1 = fmaf(xa.y, wv1[it].y, s1);
                    s1 = fmaf(xa.z, wv1[it].z, s1); s1 = fmaf(xa.w, wv1[it].w, s1);
                    s2 = fmaf(xa.x, wv2[it].x, s2); s2 = fmaf(xa.y, wv2[it].y, s2);
                    s2 = fmaf(xa.z, wv2[it].z, s2); s2 = fmaf(xa.w, wv2[it].w, s2);
                    s3 = fmaf(xa.x, wv3[it].x, s3); s3 = fmaf(xa.y, wv3[it].y, s3);
                    s3 = fmaf(xa.z, wv3[it].z, s3); s3 = fmaf(xa.w, wv3[it].w, s3);
                    u0v = fmaf(xb.x, wv0[it].x, u0v); u0v = fmaf(xb.y, wv0[it].y, u0v);
                    u0v = fmaf(xb.z, wv0[it].z, u0v); u0v = fmaf(xb.w, wv0[it].w, u0v);
                    u1v = fmaf(xb.x, wv1[it].x, u1v); u1v = fmaf(xb.y, wv1[it].y, u1v);
                    u1v = fmaf(xb.z, wv1[it].z, u1v); u1v = fmaf(xb.w, wv1[it].w, u1v);
                    u2v = fmaf(xb.x, wv2[it].x, u2v); u2v = fmaf(xb.y, wv2[it].y, u2v);
                    u2v = fmaf(xb.z, wv2[it].z, u2v); u2v = fmaf(xb.w, wv2[it].w, u2v);
                    u3v = fmaf(xb.x, wv3[it].x, u3v); u3v = fmaf(xb.y, wv3[it].y, u3v);
                    u3v = fmaf(xb.z, wv3[it].z, u3v); u3v = fmaf(xb.w, wv3[it].w, u3v);
                }
                #pragma unroll
                for (int off = 16; off; off >>= 1) {
                    s0 += __shfl_xor_sync(0xffffffffu, s0, off);
                    s1 += __shfl_xor_sync(0xffffffffu, s1, off);
                    s2 += __shfl_xor_sync(0xffffffffu, s2, off);
                    s3 += __shfl_xor_sync(0xffffffffu, s3, off);
                    u0v += __shfl_xor_sync(0xffffffffu, u0v, off);
                    u1v += __shfl_xor_sync(0xffffffffu, u1v, off);
                    u2v += __shfl_xor_sync(0xffffffffu, u2v, off);
                    u3v += __shfl_xor_sync(0xffffffffu, u3v, off);
                }
                if (lane == 0) {
                    g_z[r] = make_float4(s0, s1, s2, s3);
                    if (two) g_z[r2] = make_float4(u0v, u1v, u2v, u3v);
                }
                done += two ? 2 : 1;
            }
            if (lane == 0 && done) red_release(&g_zcnt[c], (unsigned)done);
        }
    }

    // -------- PHASE 2: broadcast, chunk-by-chunk gated on g_dw --------
    {
        float4* out = a.out;
        const int stride = (a.G - 1) * 256;
        const int self   = (bid - 1) * 256 + tid;

        for (int c = 0; c < NCH; ++c) {
            if (tid == 0) {
                while (ld_acq(&g_dw[0]) < (unsigned)(c + 1) ||
                       ld_acq(&g_dw[1]) < (unsigned)(c + 1) ||
                       ld_acq(&g_dw[2]) < (unsigned)(c + 1) ||
                       ld_acq(&g_dw[3]) < (unsigned)(c + 1)) __nanosleep(128);
            }
            __syncthreads();
            const int base = c * REG4;
            const int end  = base + REG4;
            #pragma unroll 2
            for (int i = base + self; i < end; i += stride) {
                float v = g_h[i >> 7];
                out[i] = make_float4(v, v, v, v);
            }
        }
        // hx + cx (g_dw==8 everywhere implies cfin + all h published)
        const int base = NCH * REG4;   // == ROWS*128
        for (int i = base + self; i < a.n4; i += stride) {
            int row = i >> 7;
            float v;
            if (row < ROWS + BATCH) v = g_h[row - BATCH];            // hx = h at t=255
            else                    v = g_cfin[row - ROWS - BATCH];  // cx
            out[i] = make_float4(v, v, v, v);
        }
    }
}

// ---------------- launch ----------------
extern "C" void kernel_launch(void* const* d_in, const int* in_sizes, int n_in,
                              void* d_out, int out_size) {
    static int s_sm = -1;
    const int DYN = NBUF * SEQ_T * BATCH * (int)sizeof(float4);   // 64 KB
    if (s_sm < 0) {
        int dev = 0;
        cudaGetDevice(&dev);
        cudaDeviceGetAttribute(&s_sm, cudaDevAttrMultiProcessorCount, dev);
        if (s_sm <= 0) s_sm = 148;
        cudaFuncSetAttribute(fused_kernel,
                             cudaFuncAttributeMaxDynamicSharedMemorySize, DYN);
    }
    const int G  = s_sm;               // occupancy 1: every block owns an SM
    const int Wp = (G - 1) * 8;

    Args a;
    a.x = (const float*)d_in[0];
    a.W[0] = (const float*)d_in[1];  a.b[0] = (const float*)d_in[2];  a.P[0] = (const float*)d_in[3];
    a.W[1] = (const float*)d_in[4];  a.b[1] = (const float*)d_in[5];  a.P[1] = (const float*)d_in[6];
    a.W[2] = (const float*)d_in[7];  a.b[2] = (const float*)d_in[8];  a.P[2] = (const float*)d_in[9];
    a.W[3] = (const float*)d_in[10]; a.b[3] = (const float*)d_in[11]; a.P[3] = (const float*)d_in[12];
    a.out = (float4*)d_out;
    a.G   = G;
    a.Wp  = Wp;
    a.n4  = out_size / 4;

    init_kernel<<<1, 32>>>();
    fused_kernel<<<G, 256, DYN>>>(a);
}